// round 17
// baseline (speedup 1.0000x reference)
#include <cuda_runtime.h>
#include <cuda_bf16.h>
#include <cuda_fp16.h>
#include <cstdint>
#include <math.h>

#define S_LEN 4096
#define HID   2048
#define NH    16
#define NKV   8
#define HD    128
#define QD    (NH*HD)    // 2048
#define KD    (NKV*HD)   // 1024
#define QKV_N 4096       // fused projection width: q(2048)|k(1024)|v(1024)
#define WINDOW 1024
#define SCALING 0.08838834764831845f  // 128^-0.5
#define SOFTCAP 50.0f
#define TANHF2 (2.0f*SCALING/SOFTCAP)

#define BK    32
#define NITER (HID/BK)   // 64: single-pass fp16 GEMM

// ---------------- scratch (static device globals; no runtime alloc) ----------
__device__ __half g_a16[S_LEN*HID];             // 16 MB activations fp16 (reused)
__device__ __half g_wqkv[QKV_N*HID];            // 16 MB fp16 weights (rows q|k|v)
__device__ __half g_wo[HID*QD];                 // 8 MB  fp16 Wo^T
__device__ __half g_qh[S_LEN*QD];               // 16 MB (post-rope fp16)
__device__ __half g_kh[S_LEN*KD];               // 8 MB
__device__ __half g_vh[S_LEN*KD];               // 8 MB

// ---------------- helpers ----------------------------------------------------
__device__ __forceinline__ uint32_t smem_u32(const void* p) {
    uint32_t a;
    asm("{ .reg .u64 t; cvta.to.shared.u64 t, %1; cvt.u32.u64 %0, t; }" : "=r"(a) : "l"(p));
    return a;
}
__device__ __forceinline__ void cpasync16(uint32_t saddr, const void* g) {
    asm volatile("cp.async.cg.shared.global [%0], [%1], 16;" :: "r"(saddr), "l"(g));
}
__device__ __forceinline__ void cp_commit() {
    asm volatile("cp.async.commit_group;" ::: "memory");
}
__device__ __forceinline__ void ldmatrix_x4(uint32_t* r, uint32_t addr) {
    asm volatile("ldmatrix.sync.aligned.m8n8.x4.shared.b16 {%0,%1,%2,%3}, [%4];"
                 : "=r"(r[0]), "=r"(r[1]), "=r"(r[2]), "=r"(r[3]) : "r"(addr));
}
__device__ __forceinline__ void ldmatrix_x4_t(uint32_t* r, uint32_t addr) {
    asm volatile("ldmatrix.sync.aligned.m8n8.x4.trans.shared.b16 {%0,%1,%2,%3}, [%4];"
                 : "=r"(r[0]), "=r"(r[1]), "=r"(r[2]), "=r"(r[3]) : "r"(addr));
}
__device__ __forceinline__ void mma_f16(float* d, const uint32_t* a, const uint32_t* b) {
    asm volatile(
        "mma.sync.aligned.m16n8k16.row.col.f32.f16.f16.f32 "
        "{%0,%1,%2,%3}, {%4,%5,%6,%7}, {%8,%9}, {%0,%1,%2,%3};"
        : "+f"(d[0]), "+f"(d[1]), "+f"(d[2]), "+f"(d[3])
        : "r"(a[0]), "r"(a[1]), "r"(a[2]), "r"(a[3]), "r"(b[0]), "r"(b[1]));
}

// ---------------------------------------------------------------------------
// conv_act: fp32 -> fp16 elementwise (vectorized x4)
// ---------------------------------------------------------------------------
__global__ void conv_act(const float* __restrict__ X, __half* __restrict__ A,
                         int total4) {
    int idx = blockIdx.x * blockDim.x + threadIdx.x;
    if (idx >= total4) return;
    float4 v = reinterpret_cast<const float4*>(X)[idx];
    __half2 lo = __floats2half2_rn(v.x, v.y);
    __half2 hi = __floats2half2_rn(v.z, v.w);
    uint2 out;
    out.x = *reinterpret_cast<uint32_t*>(&lo);
    out.y = *reinterpret_cast<uint32_t*>(&hi);
    reinterpret_cast<uint2*>(A)[idx] = out;
}

// All four weights in one launch; blockIdx.z selects the matrix.
__global__ void wt_f16_all(const float* __restrict__ Wq, const float* __restrict__ Wk,
                           const float* __restrict__ Wv, const float* __restrict__ Wo,
                           __half* __restrict__ wqkv, __half* __restrict__ wo) {
    const float* W; __half* B2; int Ndim;
    switch (blockIdx.z) {
        case 0:  W = Wq; B2 = wqkv;                              Ndim = QD; break;
        case 1:  W = Wk; B2 = wqkv + (size_t)QD * HID;           Ndim = KD; break;
        case 2:  W = Wv; B2 = wqkv + (size_t)(QD + KD) * HID;    Ndim = KD; break;
        default: W = Wo; B2 = wo;                                Ndim = QD; break;
    }
    int n0 = blockIdx.x * 32;
    if (n0 >= Ndim) return;
    __shared__ float tile[32][33];
    int k0 = blockIdx.y * 32;
    int tx = threadIdx.x, ty = threadIdx.y;   // 32 x 8
    #pragma unroll
    for (int i = 0; i < 32; i += 8)
        tile[ty + i][tx] = W[(size_t)(k0 + ty + i) * Ndim + n0 + tx];
    __syncthreads();
    #pragma unroll
    for (int i = 0; i < 32; i += 8) {
        int n = n0 + ty + i, k = k0 + tx;
        B2[(size_t)n * HID + k] = __float2half(tile[tx][ty + i]);
    }
}

// ---------------------------------------------------------------------------
// fp16 mma.sync GEMM, BM=BN=128, BK=32, 4-stage cp.async, 512 threads.
// mode 0: C fp32 plain write (O-projection).
// mode 1: fused RoPE epilogue -> qh/kh/vh fp16 (QKV projection). Each 128-wide
//         N tile is exactly one head; RoPE pair (d, d+64) stays in-tile.
// ---------------------------------------------------------------------------
#define TSTRIDE 80
#define A_STAGE (128*TSTRIDE)            // 10240
#define B_STAGE (128*TSTRIDE)            // 10240
#define STAGE_B (A_STAGE + B_STAGE)      // 20480
#define SM_GEMM (4*STAGE_B)              // 81920 (>= 128*132*4 = 67584 epilogue tile)
#define SROW    132                      // fp32 epilogue smem row stride

__global__ __launch_bounds__(512, 1)
void gemm_f16(const __half* __restrict__ A,
              const __half* __restrict__ B2,
              float* __restrict__ C, int N, int mode,
              __half* __restrict__ qh, __half* __restrict__ kh,
              __half* __restrict__ vh,
              const float* __restrict__ cosb, const float* __restrict__ sinb) {
    extern __shared__ __align__(16) char smem[];
    const uint32_t sbase = smem_u32(smem);

    const int tid = threadIdx.x;
    const int wid = tid >> 5;
    const int lid = tid & 31;
    const int m0 = blockIdx.y * 128;
    const int n0 = blockIdx.x * 128;
    const int wm = (wid & 3) * 32;     // 4 warp rows
    const int wn = (wid >> 2) * 32;    // 4 warp cols

    const int arow = tid >> 2;          // 0..127
    const int ac   = tid & 3;
    const __half* Abase = A + (size_t)(m0 + arow) * HID + ac * 8;
    const __half* Bbase = B2 + (size_t)(n0 + arow) * HID + ac * 8;
    const uint32_t sA = sbase + arow * TSTRIDE + ac * 16;
    const uint32_t sB = sA + A_STAGE;

    auto issue = [&](int c, int st) {
        const size_t ko = (size_t)c * BK;
        const uint32_t so = (uint32_t)st * STAGE_B;
        cpasync16(sA + so, Abase + ko);
        cpasync16(sB + so, Bbase + ko);
    };

    float acc[2][4][4];
    #pragma unroll
    for (int i = 0; i < 2; i++)
        #pragma unroll
        for (int j = 0; j < 4; j++)
            #pragma unroll
            for (int r = 0; r < 4; r++) acc[i][j][r] = 0.0f;

    const uint32_t aAddr = sbase + (wm + (lid & 15)) * TSTRIDE + (lid >> 4) * 16;
    const uint32_t bAddr = sbase + A_STAGE
        + (wn + (lid & 7) + ((lid >> 4) & 1) * 8) * TSTRIDE + ((lid >> 3) & 1) * 16;

    issue(0, 0); cp_commit();
    issue(1, 1); cp_commit();
    issue(2, 2); cp_commit();

    for (int c = 0; c < NITER; c++) {
        asm volatile("cp.async.wait_group 2;" ::: "memory");
        __syncthreads();
        if (c + 3 < NITER) issue(c + 3, (c + 3) & 3);
        cp_commit();

        const uint32_t so = (uint32_t)(c & 3) * STAGE_B;
        #pragma unroll
        for (int ks = 0; ks < 2; ks++) {
            uint32_t afr[2][4], bfr[2][4];
            #pragma unroll
            for (int mt = 0; mt < 2; mt++)
                ldmatrix_x4(afr[mt], aAddr + so + mt * (16 * TSTRIDE) + ks * 32);
            #pragma unroll
            for (int ntp = 0; ntp < 2; ntp++)
                ldmatrix_x4(bfr[ntp], bAddr + so + ntp * (16 * TSTRIDE) + ks * 32);
            #pragma unroll
            for (int mt = 0; mt < 2; mt++)
                #pragma unroll
                for (int ntp = 0; ntp < 2; ntp++) {
                    mma_f16(acc[mt][2 * ntp],     afr[mt], bfr[ntp]);
                    mma_f16(acc[mt][2 * ntp + 1], afr[mt], bfr[ntp] + 2);
                }
        }
    }

    const int erow = (lid >> 2);
    const int ecol = (lid & 3) * 2;

    if (mode == 0) {
        // plain fp32 epilogue (O projection)
        #pragma unroll
        for (int mt = 0; mt < 2; mt++) {
            #pragma unroll
            for (int nt = 0; nt < 4; nt++) {
                int r = m0 + wm + mt * 16 + erow;
                int col = n0 + wn + nt * 8 + ecol;
                *(float2*)&C[(size_t)r * N + col] = make_float2(acc[mt][nt][0], acc[mt][nt][1]);
                *(float2*)&C[(size_t)(r + 8) * N + col] = make_float2(acc[mt][nt][2], acc[mt][nt][3]);
            }
        }
        return;
    }

    // fused RoPE epilogue: stage tile fp32 in smem, then pairwise rotate + fp16
    float* sm32 = reinterpret_cast<float*>(smem);
    __syncthreads();   // all warps done with pipeline smem
    #pragma unroll
    for (int mt = 0; mt < 2; mt++) {
        #pragma unroll
        for (int nt = 0; nt < 4; nt++) {
            int r = wm + mt * 16 + erow;
            int col = wn + nt * 8 + ecol;
            *(float2*)&sm32[r * SROW + col] = make_float2(acc[mt][nt][0], acc[mt][nt][1]);
            *(float2*)&sm32[(r + 8) * SROW + col] = make_float2(acc[mt][nt][2], acc[mt][nt][3]);
        }
    }
    __syncthreads();

    // pair loop: 128 rows x 64 pairs = 8192; 16 per thread
    #pragma unroll
    for (int i = 0; i < 16; i++) {
        int p = tid + i * 512;
        int r = p >> 6, d = p & 63;
        int s = m0 + r;
        float x1 = sm32[r * SROW + d];
        float x2 = sm32[r * SROW + d + 64];
        if (n0 < QD) {          // q head (n0 == h*HD)
            float c = cosb[s * HD + d], sn = sinb[s * HD + d];
            size_t o = (size_t)s * QD + n0 + d;
            qh[o]      = __float2half(x1 * c - x2 * sn);
            qh[o + 64] = __float2half(x2 * c + x1 * sn);
        } else if (n0 < QD + KD) {  // k head
            float c = cosb[s * HD + d], sn = sinb[s * HD + d];
            size_t o = (size_t)s * KD + (n0 - QD) + d;
            kh[o]      = __float2half(x1 * c - x2 * sn);
            kh[o + 64] = __float2half(x2 * c + x1 * sn);
        } else {                // v head: plain convert
            size_t o = (size_t)s * KD + (n0 - QD - KD) + d;
            vh[o]      = __float2half(x1);
            vh[o + 64] = __float2half(x2);
        }
    }
}

// ---------------------------------------------------------------------------
// Tensor-core flash attention, pure fp16 single-pass, sliding window + softcap.
// ---------------------------------------------------------------------------
#define RSTR   272
#define STG_OFF 34816                 // Qh region (128*272)
#define KSTG   17408                  // 64*272
#define STG_SZ 34816                  // Kh+Vh per stage
#define ATTN_SMEM (STG_OFF + 2*STG_SZ)  // 104448

__global__ __launch_bounds__(256, 2)
void attn_tc(const __half* __restrict__ Qh,
             const __half* __restrict__ Kh, const __half* __restrict__ Vh,
             __half* __restrict__ Out) {
    extern __shared__ __align__(16) char smem[];
    const uint32_t sb = smem_u32(smem);
    const int tid = threadIdx.x, wid = tid >> 5, lid = tid & 31;
    const int h = blockIdx.y, q0 = blockIdx.x * 128, kvh = h >> 1;

    #pragma unroll
    for (int i = 0; i < 8; i++) {
        int id = tid + i * 256;
        int row = id >> 4, c = id & 15;
        cpasync16(sb + row * RSTR + c * 16,
                  Qh + (size_t)(q0 + row) * QD + h * HD + c * 8);
    }

    int jmin = q0 - (WINDOW - 1); if (jmin < 0) jmin = 0;
    const int t0 = jmin >> 6, t1 = (q0 + 127) >> 6;

    auto issueKV = [&](int t, int st) {
        const int kt = t << 6;
        const uint32_t sbase = sb + STG_OFF + (uint32_t)st * STG_SZ;
        #pragma unroll
        for (int i = 0; i < 8; i++) {
            int id = tid + i * 256;
            int mat = id >> 10, id2 = id & 1023;    // 0=Kh, 1=Vh
            int row = id2 >> 4, c = id2 & 15;
            const __half* base = mat ? Vh : Kh;
            cpasync16(sbase + mat * KSTG + row * RSTR + c * 16,
                      base + (size_t)(kt + row) * KD + kvh * HD + c * 8);
        }
    };
    issueKV(t0, 0); cp_commit();

    float o[16][4];
    #pragma unroll
    for (int i = 0; i < 16; i++)
        #pragma unroll
        for (int j = 0; j < 4; j++) o[i][j] = 0.0f;
    float m0 = -1e30f, m1 = -1e30f, l0 = 0.0f, l1 = 0.0f;

    const int wm = wid * 16;
    const int i0 = q0 + wm + (lid >> 2), i1 = i0 + 8;
    const uint32_t qa_h = sb + (wm + (lid & 15)) * RSTR + (lid >> 4) * 16;
    const uint32_t ka_row = (lid & 7) + ((lid >> 4) & 1) * 8;
    const uint32_t ka_coff = ((lid >> 3) & 1) * 16;
    const uint32_t v_row = (lid & 7) + ((lid >> 3) & 1) * 8;
    const uint32_t v_coff = ((lid >> 4) & 1) * 16;

    int st = 0;
    for (int t = t0; t <= t1; t++) {
        if (t < t1) { issueKV(t + 1, st ^ 1); cp_commit(); }
        if (t < t1) asm volatile("cp.async.wait_group 1;" ::: "memory");
        else        asm volatile("cp.async.wait_group 0;" ::: "memory");
        __syncthreads();

        const uint32_t stg = sb + STG_OFF + (uint32_t)st * STG_SZ;

        float sf[8][4];
        #pragma unroll
        for (int nt = 0; nt < 8; nt++)
            #pragma unroll
            for (int j = 0; j < 4; j++) sf[nt][j] = 0.0f;

        // S = Qh·Kh^T
        #pragma unroll
        for (int kk = 0; kk < 8; kk++) {
            uint32_t a[4];
            ldmatrix_x4(a, qa_h + kk * 32);
            #pragma unroll
            for (int ntp = 0; ntp < 4; ntp++) {
                uint32_t b[4];
                ldmatrix_x4(b, stg + (ntp * 16 + ka_row) * RSTR + ka_coff + kk * 32);
                mma_f16(sf[2 * ntp],     a, b);
                mma_f16(sf[2 * ntp + 1], a, b + 2);
            }
        }

        const int jt = t << 6;
        float mx0 = -1e30f, mx1 = -1e30f;
        #pragma unroll
        for (int nt = 0; nt < 8; nt++) {
            int jb = jt + nt * 8 + ((lid & 3) << 1);
            #pragma unroll
            for (int vv = 0; vv < 4; vv++) {
                int jj = jb + (vv & 1);
                int ii = (vv < 2) ? i0 : i1;
                float e = __expf(sf[nt][vv] * TANHF2);
                float val = SOFTCAP * __fdividef(e - 1.0f, e + 1.0f);
                bool ok = (jj <= ii) && (ii - jj < WINDOW);
                sf[nt][vv] = ok ? val : -1e30f;
            }
            mx0 = fmaxf(mx0, fmaxf(sf[nt][0], sf[nt][1]));
            mx1 = fmaxf(mx1, fmaxf(sf[nt][2], sf[nt][3]));
        }
        mx0 = fmaxf(mx0, __shfl_xor_sync(0xffffffffu, mx0, 1));
        mx0 = fmaxf(mx0, __shfl_xor_sync(0xffffffffu, mx0, 2));
        mx1 = fmaxf(mx1, __shfl_xor_sync(0xffffffffu, mx1, 1));
        mx1 = fmaxf(mx1, __shfl_xor_sync(0xffffffffu, mx1, 2));

        float mn0 = fmaxf(m0, mx0), mn1 = fmaxf(m1, mx1);
        float sc0 = __expf(m0 - mn0), sc1 = __expf(m1 - mn1);
        m0 = mn0; m1 = mn1;

        float s0 = 0.0f, s1 = 0.0f;
        uint32_t phA[8], phB[8];
        #pragma unroll
        for (int nt = 0; nt < 8; nt++) {
            float p0 = __expf(sf[nt][0] - mn0), p1 = __expf(sf[nt][1] - mn0);
            float p2 = __expf(sf[nt][2] - mn1), p3 = __expf(sf[nt][3] - mn1);
            s0 += p0 + p1; s1 += p2 + p3;
            __half2 hA = __floats2half2_rn(p0, p1);
            __half2 hB = __floats2half2_rn(p2, p3);
            phA[nt] = *reinterpret_cast<uint32_t*>(&hA);
            phB[nt] = *reinterpret_cast<uint32_t*>(&hB);
        }
        s0 += __shfl_xor_sync(0xffffffffu, s0, 1);
        s0 += __shfl_xor_sync(0xffffffffu, s0, 2);
        s1 += __shfl_xor_sync(0xffffffffu, s1, 1);
        s1 += __shfl_xor_sync(0xffffffffu, s1, 2);
        l0 = l0 * sc0 + s0;
        l1 = l1 * sc1 + s1;

        #pragma unroll
        for (int nt = 0; nt < 16; nt++) {
            o[nt][0] *= sc0; o[nt][1] *= sc0;
            o[nt][2] *= sc1; o[nt][3] *= sc1;
        }

        // O += Ph·Vh
        const uint32_t vb = stg + KSTG;
        #pragma unroll
        for (int kk = 0; kk < 4; kk++) {
            uint32_t a[4] = { phA[2 * kk], phB[2 * kk], phA[2 * kk + 1], phB[2 * kk + 1] };
            #pragma unroll
            for (int np = 0; np < 8; np++) {
                uint32_t b[4];
                ldmatrix_x4_t(b, vb + (kk * 16 + v_row) * RSTR + np * 32 + v_coff);
                mma_f16(o[2 * np],     a, b);
                mma_f16(o[2 * np + 1], a, b + 2);
            }
        }
        __syncthreads();
        st ^= 1;
    }

    // epilogue: normalize + write fp16 rows into a16 [S, HID]
    const float inv0 = 1.0f / l0, inv1 = 1.0f / l1;
    #pragma unroll
    for (int nt = 0; nt < 16; nt++) {
        int col = h * HD + nt * 8 + ((lid & 3) << 1);
        {
            __half2 hh = __floats2half2_rn(o[nt][0] * inv0, o[nt][1] * inv0);
            reinterpret_cast<uint32_t*>(Out + (size_t)i0 * HID)[col >> 1] =
                *reinterpret_cast<uint32_t*>(&hh);
        }
        {
            __half2 hh = __floats2half2_rn(o[nt][2] * inv1, o[nt][3] * inv1);
            reinterpret_cast<uint32_t*>(Out + (size_t)i1 * HID)[col >> 1] =
                *reinterpret_cast<uint32_t*>(&hh);
        }
    }
}

// ---------------------------------------------------------------------------
extern "C" void kernel_launch(void* const* d_in, const int* in_sizes, int n_in,
                              void* d_out, int out_size) {
    const float* hs   = (const float*)d_in[0];
    const float* cosb = (const float*)d_in[1];
    const float* sinb = (const float*)d_in[2];
    // d_in[3] = attention_mask (unused; mask computed analytically)
    const float* Wq = (const float*)d_in[4];
    const float* Wk = (const float*)d_in[5];
    const float* Wv = (const float*)d_in[6];
    const float* Wo = (const float*)d_in[7];
    float* out = (float*)d_out;

    __half *a16, *wqkv, *wo, *qh, *kh, *vh;
    cudaGetSymbolAddress((void**)&a16,  g_a16);
    cudaGetSymbolAddress((void**)&wqkv, g_wqkv);
    cudaGetSymbolAddress((void**)&wo,   g_wo);
    cudaGetSymbolAddress((void**)&qh,   g_qh);
    cudaGetSymbolAddress((void**)&kh,   g_kh);
    cudaGetSymbolAddress((void**)&vh,   g_vh);

    cudaFuncSetAttribute(gemm_f16, cudaFuncAttributeMaxDynamicSharedMemorySize, SM_GEMM);
    cudaFuncSetAttribute(attn_tc, cudaFuncAttributeMaxDynamicSharedMemorySize, ATTN_SMEM);

    // conversions (one fused weight launch; z selects matrix)
    conv_act<<<(S_LEN*HID/4 + 255)/256, 256>>>(hs, a16, S_LEN*HID/4);
    wt_f16_all<<<dim3(QD/32, HID/32, 4), dim3(32, 8)>>>(Wq, Wk, Wv, Wo, wqkv, wo);

    // fused QKV projection + RoPE + fp16 epilogue (mode 1)
    gemm_f16<<<dim3(QKV_N/128, S_LEN/128), 512, SM_GEMM>>>(
        a16, wqkv, nullptr, QKV_N, 1, qh, kh, vh, cosb, sinb);

    // tensor-core attention (pure fp16) -> writes fp16 activations into a16
    attn_tc<<<dim3(S_LEN/128, NH), 256, ATTN_SMEM>>>(qh, kh, vh, a16);

    // output projection (mode 0, fp32 out)
    gemm_f16<<<dim3(HID/128, S_LEN/128), 512, SM_GEMM>>>(
        a16, wo, out, HID, 0, nullptr, nullptr, nullptr, nullptr, nullptr);
}